// round 2
// baseline (speedup 1.0000x reference)
#include <cuda_runtime.h>
#include <cstdint>

// Problem constants
#define B_   4
#define C_   64
#define HL   64      // low-res h = w
#define HH   256     // high-res H = W
#define S_   4       // scale
#define NPIX (HH*HH)         // 65536
#define GN   (3*HH*HH)       // guidance elems per batch = 196608
#define INV2SS2 0.08f        // 1/(2*2.5^2)

// ---------------- scratch (static device globals; no allocation) ----------------
__device__ float g_part[B_][64][2];     // per-block partial (sum, sumsq)
__device__ float g_inv2sr2[B_];         // 1/(2*sigma_range^2) per batch
__device__ float g_srcT[B_ * HL * HL * C_];  // source transposed to (b,y,x,c)  (4 MB)

// ---------------- reduction 1: partial sums of guidance per batch ----------------
__global__ __launch_bounds__(256) void jbu_reduce1(const float* __restrict__ guid) {
    const int b = blockIdx.y;
    const float* p = guid + (size_t)b * GN + (size_t)blockIdx.x * (GN / 64);
    float s = 0.f, s2 = 0.f;
    for (int i = threadIdx.x; i < GN / 64; i += 256) {
        float v = p[i];
        s += v; s2 += v * v;
    }
    #pragma unroll
    for (int o = 16; o; o >>= 1) {
        s  += __shfl_xor_sync(0xffffffffu, s,  o);
        s2 += __shfl_xor_sync(0xffffffffu, s2, o);
    }
    __shared__ float sh[8][2];
    const int w = threadIdx.x >> 5;
    if ((threadIdx.x & 31) == 0) { sh[w][0] = s; sh[w][1] = s2; }
    __syncthreads();
    if (threadIdx.x == 0) {
        float ts = 0.f, ts2 = 0.f;
        #pragma unroll
        for (int i = 0; i < 8; i++) { ts += sh[i][0]; ts2 += sh[i][1]; }
        g_part[b][blockIdx.x][0] = ts;
        g_part[b][blockIdx.x][1] = ts2;
    }
}

// ---------------- reduction 2: finalize inv_2sr2 (deterministic, double) ----------------
__global__ void jbu_reduce2() {
    const int b = threadIdx.x;
    if (b < B_) {
        double s = 0.0, s2 = 0.0;
        for (int i = 0; i < 64; i++) { s += (double)g_part[b][i][0]; s2 += (double)g_part[b][i][1]; }
        const double N = (double)GN;
        double var = (s2 - s * s / N) / (N - 1.0);
        // sigma_range = 0.5*sigma_g  ->  1/(2*sr^2) = 1/(0.5*var) = 2/var
        g_inv2sr2[b] = (float)(2.0 / var);
    }
}

// ---------------- transpose source: (b,c,y,x) -> (b,y,x,c) ----------------
// Treat per-batch as 64 x 4096 matrix -> 4096 x 64.
__global__ __launch_bounds__(256) void jbu_transpose(const float* __restrict__ src) {
    __shared__ float tile[32][33];
    const int b  = blockIdx.z;
    const int p0 = blockIdx.x * 32;   // pixel block (0..4095)
    const int c0 = blockIdx.y * 32;   // channel block (0..63)
    const int tx = threadIdx.x, ty = threadIdx.y;   // 32 x 8
    #pragma unroll
    for (int i = 0; i < 32; i += 8)
        tile[ty + i][tx] = src[((size_t)b * C_ + (c0 + ty + i)) * (HL * HL) + (p0 + tx)];
    __syncthreads();
    #pragma unroll
    for (int i = 0; i < 32; i += 8)
        g_srcT[((size_t)b * (HL * HL) + (p0 + ty + i)) * C_ + (c0 + tx)] = tile[tx][ty + i];
}

// ---------------- main JBU kernel ----------------
// Block: 256 threads, output tile = 4 rows (one low-res cell row) x 64 cols (16 cells).
// Grid: (W/64=4, H/4=64, B=4)
__global__ __launch_bounds__(256) void jbu_main(
    const float* __restrict__ guid,   // (4,3,256,256)
    float* __restrict__ out)          // (4,64,256,256)
{
    const int b     = blockIdx.z;
    const int cellY = blockIdx.y;         // 0..63
    const int cx0   = blockIdx.x * 16;    // first low-res cell x
    const int x0    = cx0 * 4;

    __shared__ float s_src[100][C_];      // [yl*20+xl][c]  (25.6 KB)
    __shared__ float s_gl[3][5][20];      // g_low tile
    __shared__ float s_inv;

    const int tid = threadIdx.x;
    if (tid == 0) s_inv = g_inv2sr2[b];

    // preload g_low tile: g_low[b][c][yi][xi] = guid[b][c][4*yi+2][4*xi+2]
    for (int i = tid; i < 300; i += 256) {
        int c  = i / 100;
        int rm = i % 100;
        int yl = rm / 20, xl = rm % 20;
        int yi = min(max(cellY + yl - 2, 0), HL - 1);
        int xi = min(max(cx0   + xl - 2, 0), HL - 1);
        s_gl[c][yl][xl] = guid[(((size_t)b * 3 + c) * HH + (4 * yi + 2)) * HH + (4 * xi + 2)];
    }

    // preload src tile (channels-last): 100 positions x 16 float4
    {
        const float4* sp = (const float4*)g_srcT;
        float4*       dp = (float4*)s_src;
        for (int i = tid; i < 1600; i += 256) {
            int p  = i >> 4, c4 = i & 15;
            int yl = p / 20, xl = p % 20;
            int yi = min(max(cellY + yl - 2, 0), HL - 1);
            int xi = min(max(cx0   + xl - 2, 0), HL - 1);
            dp[(p << 4) + c4] = sp[((((size_t)b * HL + yi) * HL + xi) << 4) + c4];
        }
    }
    __syncthreads();

    // ---- phase 1: per-pixel weights (kept in registers) ----
    const int r   = tid >> 6;        // 0..3
    const int col = tid & 63;        // 0..63
    const int y   = cellY * 4 + r;
    const int x   = x0 + col;
    const int clx = col >> 2;        // local cell x 0..15
    const float inv2sr2 = s_inv;

    const float g0 = guid[(((size_t)b * 3 + 0) * HH + y) * HH + x];
    const float g1 = guid[(((size_t)b * 3 + 1) * HH + y) * HH + x];
    const float g2 = guid[(((size_t)b * 3 + 2) * HH + y) * HH + x];

    float w[25];
    int   pos[25];
    float den = 0.f;
    #pragma unroll
    for (int dy = 0; dy < 5; dy++) {
        #pragma unroll
        for (int dx = 0; dx < 5; dx++) {
            const int t  = dy * 5 + dx;
            const int xl = clx + dx;             // 0..19
            float d0 = g0 - s_gl[0][dy][xl];
            float d1 = g1 - s_gl[1][dy][xl];
            float d2 = g2 - s_gl[2][dy][xl];
            float diff2 = d0 * d0 + d1 * d1 + d2 * d2;
            float sp2 = (float)((dy - 2) * (dy - 2) + (dx - 2) * (dx - 2));
            float wt = __expf(-sp2 * INV2SS2 - diff2 * inv2sr2);
            w[t]  = wt;
            den  += wt;
            pos[t] = ((dy * 20) + xl) << 4;      // float4 row base into s_src
        }
    }
    const float invden = 1.0f / (den + 1e-8f);
    #pragma unroll
    for (int t = 0; t < 25; t++) w[t] *= invden;

    // ---- phase 2: weighted channel sums ----
    float* op = out + (((size_t)b * C_) * HH + y) * HH + x;
    const float4* sp4 = (const float4*)s_src;
    for (int cg = 0; cg < 16; cg++) {
        float ax = 0.f, ay = 0.f, az = 0.f, aw = 0.f;
        #pragma unroll
        for (int t = 0; t < 25; t++) {
            float4 s = sp4[pos[t] + cg];
            ax += w[t] * s.x;
            ay += w[t] * s.y;
            az += w[t] * s.z;
            aw += w[t] * s.w;
        }
        op[(size_t)(4 * cg + 0) * NPIX] = ax;
        op[(size_t)(4 * cg + 1) * NPIX] = ay;
        op[(size_t)(4 * cg + 2) * NPIX] = az;
        op[(size_t)(4 * cg + 3) * NPIX] = aw;
    }
}

// ---------------- launch ----------------
extern "C" void kernel_launch(void* const* d_in, const int* in_sizes, int n_in,
                              void* d_out, int out_size) {
    const float* src  = (const float*)d_in[0];
    const float* guid = (const float*)d_in[1];
    // robustness to metadata ordering
    if (n_in >= 2 && in_sizes[0] == B_ * GN) {
        const float* tmp = src; src = guid; guid = tmp;
    }
    float* out = (float*)d_out;

    jbu_reduce1<<<dim3(64, B_), 256>>>(guid);
    jbu_reduce2<<<1, 32>>>();
    jbu_transpose<<<dim3(128, 2, B_), dim3(32, 8)>>>(src);
    jbu_main<<<dim3(HH / 64, HH / S_, B_), 256>>>(guid, out);
}

// round 5
// speedup vs baseline: 2.1061x; 2.1061x over previous
#include <cuda_runtime.h>
#include <cstdint>

// Problem constants
#define B_   4
#define C_   64
#define HL   64      // low-res h = w
#define HH   256     // high-res H = W
#define S_   4       // scale
#define NPIX (HH*HH)         // 65536
#define GN   (3*HH*HH)       // guidance elems per batch = 196608
#define INV2SS2 0.08f        // 1/(2*2.5^2)

// Padded s_src row stride in float4/ulonglong2 units: 17 (=272B).
// Distinct warp addresses then step 272B -> banks {0,4,...,28}: conflict-free.
#define ROW4 17

// ---------------- scratch (static device globals; no allocation) ----------------
__device__ float g_part[B_][64][2];     // per-block partial (sum, sumsq)
__device__ float g_inv2sr2[B_];         // 1/(2*sigma_range^2) per batch
__device__ float g_srcT[B_ * HL * HL * C_];  // source transposed to (b,y,x,c)  (4 MB)

// ---------------- reduction 1: partial sums of guidance per batch ----------------
__global__ __launch_bounds__(256) void jbu_reduce1(const float* __restrict__ guid) {
    const int b = blockIdx.y;
    const float* p = guid + (size_t)b * GN + (size_t)blockIdx.x * (GN / 64);
    float s = 0.f, s2 = 0.f;
    for (int i = threadIdx.x; i < GN / 64; i += 256) {
        float v = p[i];
        s += v; s2 += v * v;
    }
    #pragma unroll
    for (int o = 16; o; o >>= 1) {
        s  += __shfl_xor_sync(0xffffffffu, s,  o);
        s2 += __shfl_xor_sync(0xffffffffu, s2, o);
    }
    __shared__ float sh[8][2];
    const int w = threadIdx.x >> 5;
    if ((threadIdx.x & 31) == 0) { sh[w][0] = s; sh[w][1] = s2; }
    __syncthreads();
    if (threadIdx.x == 0) {
        float ts = 0.f, ts2 = 0.f;
        #pragma unroll
        for (int i = 0; i < 8; i++) { ts += sh[i][0]; ts2 += sh[i][1]; }
        g_part[b][blockIdx.x][0] = ts;
        g_part[b][blockIdx.x][1] = ts2;
    }
}

// ---------------- reduction 2: finalize inv_2sr2 (deterministic, double) ----------------
__global__ void jbu_reduce2() {
    const int b = threadIdx.x;
    if (b < B_) {
        double s = 0.0, s2 = 0.0;
        for (int i = 0; i < 64; i++) { s += (double)g_part[b][i][0]; s2 += (double)g_part[b][i][1]; }
        const double N = (double)GN;
        double var = (s2 - s * s / N) / (N - 1.0);
        // sigma_range = 0.5*sigma_g  ->  1/(2*sr^2) = 1/(0.5*var) = 2/var
        g_inv2sr2[b] = (float)(2.0 / var);
    }
}

// ---------------- transpose source: (b,c,y,x) -> (b,y,x,c) ----------------
__global__ __launch_bounds__(256) void jbu_transpose(const float* __restrict__ src) {
    __shared__ float tile[32][33];
    const int b  = blockIdx.z;
    const int p0 = blockIdx.x * 32;   // pixel block (0..4095)
    const int c0 = blockIdx.y * 32;   // channel block (0..63)
    const int tx = threadIdx.x, ty = threadIdx.y;   // 32 x 8
    #pragma unroll
    for (int i = 0; i < 32; i += 8)
        tile[ty + i][tx] = src[((size_t)b * C_ + (c0 + ty + i)) * (HL * HL) + (p0 + tx)];
    __syncthreads();
    #pragma unroll
    for (int i = 0; i < 32; i += 8)
        g_srcT[((size_t)b * (HL * HL) + (p0 + ty + i)) * C_ + (c0 + tx)] = tile[tx][ty + i];
}

// ---------------- main JBU kernel ----------------
// Block: 256 threads, output tile = 4 rows (one low-res cell row) x 64 cols (16 cells).
// Grid: (W/64=4, H/4=64, B=4)
__global__ __launch_bounds__(256) void jbu_main(
    const float* __restrict__ guid,   // (4,3,256,256)
    float* __restrict__ out)          // (4,64,256,256)
{
    const int b     = blockIdx.z;
    const int cellY = blockIdx.y;         // 0..63
    const int cx0   = blockIdx.x * 16;    // first low-res cell x
    const int x0    = cx0 * 4;

    // padded: 100 positions x 17 float4 (68 floats), bank-conflict-free phase 2
    __shared__ __align__(16) float s_src[100 * ROW4 * 4];
    __shared__ float s_gl[3][5][20];      // g_low tile
    __shared__ float s_inv;

    const int tid = threadIdx.x;
    if (tid == 0) s_inv = g_inv2sr2[b];

    // preload g_low tile: g_low[b][c][yi][xi] = guid[b][c][4*yi+2][4*xi+2]
    for (int i = tid; i < 300; i += 256) {
        int c  = i / 100;
        int rm = i % 100;
        int yl = rm / 20, xl = rm % 20;
        int yi = min(max(cellY + yl - 2, 0), HL - 1);
        int xi = min(max(cx0   + xl - 2, 0), HL - 1);
        s_gl[c][yl][xl] = guid[(((size_t)b * 3 + c) * HH + (4 * yi + 2)) * HH + (4 * xi + 2)];
    }

    // preload src tile (channels-last): 100 positions x 16 float4 (stride ROW4)
    {
        const float4* sp = (const float4*)g_srcT;
        float4*       dp = (float4*)s_src;
        for (int i = tid; i < 1600; i += 256) {
            int p  = i >> 4, c4 = i & 15;
            int yl = p / 20, xl = p % 20;
            int yi = min(max(cellY + yl - 2, 0), HL - 1);
            int xi = min(max(cx0   + xl - 2, 0), HL - 1);
            dp[p * ROW4 + c4] = sp[((((size_t)b * HL + yi) * HL + xi) << 4) + c4];
        }
    }
    __syncthreads();

    // ---- phase 1: per-pixel weights ----
    const int r   = tid >> 6;        // 0..3
    const int col = tid & 63;        // 0..63
    const int y   = cellY * 4 + r;
    const int x   = x0 + col;
    const int clx = col >> 2;        // local cell x 0..15
    const float inv2sr2 = s_inv;

    const float g0 = guid[(((size_t)b * 3 + 0) * HH + y) * HH + x];
    const float g1 = guid[(((size_t)b * 3 + 1) * HH + y) * HH + x];
    const float g2 = guid[(((size_t)b * 3 + 2) * HH + y) * HH + x];

    float w[25];
    float den = 0.f;
    #pragma unroll
    for (int dy = 0; dy < 5; dy++) {
        #pragma unroll
        for (int dx = 0; dx < 5; dx++) {
            const int t  = dy * 5 + dx;
            const int xl = clx + dx;             // 0..19
            float d0 = g0 - s_gl[0][dy][xl];
            float d1 = g1 - s_gl[1][dy][xl];
            float d2 = g2 - s_gl[2][dy][xl];
            float diff2 = d0 * d0 + d1 * d1 + d2 * d2;
            float sp2 = (float)((dy - 2) * (dy - 2) + (dx - 2) * (dx - 2));
            float wt = __expf(-sp2 * INV2SS2 - diff2 * inv2sr2);
            w[t]  = wt;
            den  += wt;
        }
    }
    const float invden = 1.0f / (den + 1e-8f);

    // pack weights as {w,w} for fma.rn.f32x2 (25 movs/thread, one-time)
    unsigned long long wp[25];
    #pragma unroll
    for (int t = 0; t < 25; t++) {
        float wv = w[t] * invden;
        asm("mov.b64 %0, {%1, %1};" : "=l"(wp[t]) : "f"(wv));
    }

    // ---- phase 2: weighted channel sums via packed f32x2 FMA ----
    float* op = out + (((size_t)b * C_) * HH + y) * HH + x;
    const ulonglong2* sbase = (const ulonglong2*)s_src + clx * ROW4;
    for (int cg = 0; cg < 16; cg++) {
        unsigned long long axy = 0ULL, azw = 0ULL;   // {0.f,0.f}
        const ulonglong2* p = sbase + cg;
        #pragma unroll
        for (int dy = 0; dy < 5; dy++) {
            #pragma unroll
            for (int dx = 0; dx < 5; dx++) {
                const int t = dy * 5 + dx;
                ulonglong2 s = p[(dy * 20 + dx) * ROW4];   // LDS.128, imm offset
                asm("fma.rn.f32x2 %0, %1, %2, %0;" : "+l"(axy) : "l"(wp[t]), "l"(s.x));
                asm("fma.rn.f32x2 %0, %1, %2, %0;" : "+l"(azw) : "l"(wp[t]), "l"(s.y));
            }
        }
        float ax, ay, az, aw;
        asm("mov.b64 {%0, %1}, %2;" : "=f"(ax), "=f"(ay) : "l"(axy));
        asm("mov.b64 {%0, %1}, %2;" : "=f"(az), "=f"(aw) : "l"(azw));
        op[(size_t)(4 * cg + 0) * NPIX] = ax;
        op[(size_t)(4 * cg + 1) * NPIX] = ay;
        op[(size_t)(4 * cg + 2) * NPIX] = az;
        op[(size_t)(4 * cg + 3) * NPIX] = aw;
    }
}

// ---------------- launch ----------------
extern "C" void kernel_launch(void* const* d_in, const int* in_sizes, int n_in,
                              void* d_out, int out_size) {
    const float* src  = (const float*)d_in[0];
    const float* guid = (const float*)d_in[1];
    // robustness to metadata ordering
    if (n_in >= 2 && in_sizes[0] == B_ * GN) {
        const float* tmp = src; src = guid; guid = tmp;
    }
    float* out = (float*)d_out;

    jbu_reduce1<<<dim3(64, B_), 256>>>(guid);
    jbu_reduce2<<<1, 32>>>();
    jbu_transpose<<<dim3(128, 2, B_), dim3(32, 8)>>>(src);
    jbu_main<<<dim3(HH / 64, HH / S_, B_), 256>>>(guid, out);
}

// round 6
// speedup vs baseline: 2.2731x; 1.0793x over previous
#include <cuda_runtime.h>
#include <cstdint>

// Problem constants
#define B_   4
#define C_   64
#define HL   64      // low-res h = w
#define HH   256     // high-res H = W
#define NPIX (HH*HH)         // 65536
#define GN   (3*HH*HH)       // guidance elems per batch
#define INV2SS2 0.08f        // 1/(2*2.5^2)

#define ROW4  17             // padded float4 stride for s_src (272B)
#define CELLS 8              // low-res cells per block
#define XL    (CELLS + 4)    // 12 halo columns
#define POS   (5 * XL)       // 60 source positions per block

// ---------------- scratch ----------------
__device__ float g_part[B_][64][2];          // per-block partial (sum, sumsq)
__device__ float g_srcT[B_ * HL * HL * C_];  // source transposed to (b,y,x,c)

// ---------------- fused pre-pass: guidance reduction + source transpose ----------------
// grid (128, 3, B): y==2 -> reduce1 (x<64), y<2 -> transpose (c0 = y*32)
__global__ __launch_bounds__(256) void jbu_pre(const float* __restrict__ guid,
                                               const float* __restrict__ src) {
    const int b   = blockIdx.z;
    const int tid = threadIdx.x;

    if (blockIdx.y == 2) {
        if (blockIdx.x >= 64) return;
        const float* p = guid + (size_t)b * GN + (size_t)blockIdx.x * (GN / 64);
        float s = 0.f, s2 = 0.f;
        for (int i = tid; i < GN / 64; i += 256) {
            float v = p[i];
            s += v; s2 += v * v;
        }
        #pragma unroll
        for (int o = 16; o; o >>= 1) {
            s  += __shfl_xor_sync(0xffffffffu, s,  o);
            s2 += __shfl_xor_sync(0xffffffffu, s2, o);
        }
        __shared__ float sh[8][2];
        const int w = tid >> 5;
        if ((tid & 31) == 0) { sh[w][0] = s; sh[w][1] = s2; }
        __syncthreads();
        if (tid == 0) {
            float ts = 0.f, ts2 = 0.f;
            #pragma unroll
            for (int i = 0; i < 8; i++) { ts += sh[i][0]; ts2 += sh[i][1]; }
            g_part[b][blockIdx.x][0] = ts;
            g_part[b][blockIdx.x][1] = ts2;
        }
    } else {
        __shared__ float tile[32][33];
        const int p0 = blockIdx.x * 32;         // pixel block (0..4095)
        const int c0 = blockIdx.y * 32;         // channel block
        const int tx = tid & 31, ty = tid >> 5; // 32 x 8
        #pragma unroll
        for (int i = 0; i < 32; i += 8)
            tile[ty + i][tx] = src[((size_t)b * C_ + (c0 + ty + i)) * (HL * HL) + (p0 + tx)];
        __syncthreads();
        #pragma unroll
        for (int i = 0; i < 32; i += 8)
            g_srcT[((size_t)b * (HL * HL) + (p0 + ty + i)) * C_ + (c0 + tx)] = tile[tx][ty + i];
    }
}

// ---------------- main JBU kernel ----------------
// Block: 128 threads, tile = 8 low-res cells (32 hi-res cols x 4 rows).
// Grid: (HL/CELLS=8, HL=64, B)
__global__ __launch_bounds__(128) void jbu_main(
    const float* __restrict__ guid,   // (4,3,256,256)
    float* __restrict__ out)          // (4,64,256,256)
{
    const int b     = blockIdx.z;
    const int cellY = blockIdx.y;              // 0..63
    const int cx0   = blockIdx.x * CELLS;      // first low-res cell x
    const int x0    = cx0 * 4;

    __shared__ __align__(16) float s_src[POS * ROW4 * 4];   // 16320 B
    __shared__ __align__(16) float s_w[CELLS][25][16];      // 12800 B (normalized weights)
    __shared__ float s_gl[3][5][XL];                        // g_low tile
    __shared__ float s_invsh;

    const int tid = threadIdx.x;

    // preload g_low tile
    for (int i = tid; i < 3 * POS; i += 128) {
        int c  = i / POS;
        int rm = i % POS;
        int yl = rm / XL, xl = rm % XL;
        int yi = min(max(cellY + yl - 2, 0), HL - 1);
        int xi = min(max(cx0   + xl - 2, 0), HL - 1);
        s_gl[c][yl][xl] = guid[(((size_t)b * 3 + c) * HH + (4 * yi + 2)) * HH + (4 * xi + 2)];
    }

    // preload src tile (channels-last): 60 positions x 16 float4 (stride ROW4)
    {
        const float4* sp = (const float4*)g_srcT;
        float4*       dp = (float4*)s_src;
        for (int i = tid; i < POS * 16; i += 128) {
            int p  = i >> 4, c4 = i & 15;
            int yl = p / XL, xl = p % XL;
            int yi = min(max(cellY + yl - 2, 0), HL - 1);
            int xi = min(max(cx0   + xl - 2, 0), HL - 1);
            dp[p * ROW4 + c4] = sp[((((size_t)b * HL + yi) * HL + xi) << 4) + c4];
        }
    }

    // sigma finalization (warp 0, deterministic double shfl-tree)
    if (tid < 32) {
        double s  = (double)g_part[b][2 * tid][0] + (double)g_part[b][2 * tid + 1][0];
        double s2 = (double)g_part[b][2 * tid][1] + (double)g_part[b][2 * tid + 1][1];
        #pragma unroll
        for (int o = 16; o; o >>= 1) {
            s  += __shfl_xor_sync(0xffffffffu, s,  o);
            s2 += __shfl_xor_sync(0xffffffffu, s2, o);
        }
        if (tid == 0) {
            const double N = (double)GN;
            double var = (s2 - s * s / N) / (N - 1.0);
            s_invsh = (float)(2.0 / var);   // 1/(2*(0.5*sigma)^2) = 2/var
        }
    }
    __syncthreads();

    // ---- phase 1: per-pixel weights -> s_w ----
    {
        const int r   = tid >> 5;        // 0..3
        const int col = tid & 31;        // 0..31
        const int y   = cellY * 4 + r;
        const int x   = x0 + col;
        const int clx = col >> 2;        // local cell 0..7
        const int px  = r * 4 + (col & 3);
        const float inv2sr2 = s_invsh;

        const float g0 = guid[(((size_t)b * 3 + 0) * HH + y) * HH + x];
        const float g1 = guid[(((size_t)b * 3 + 1) * HH + y) * HH + x];
        const float g2 = guid[(((size_t)b * 3 + 2) * HH + y) * HH + x];

        float w[25];
        float den = 0.f;
        #pragma unroll
        for (int dy = 0; dy < 5; dy++) {
            #pragma unroll
            for (int dx = 0; dx < 5; dx++) {
                const int t  = dy * 5 + dx;
                const int xl = clx + dx;
                float d0 = g0 - s_gl[0][dy][xl];
                float d1 = g1 - s_gl[1][dy][xl];
                float d2 = g2 - s_gl[2][dy][xl];
                float diff2 = d0 * d0 + d1 * d1 + d2 * d2;
                float sp2 = (float)((dy - 2) * (dy - 2) + (dx - 2) * (dx - 2));
                float wt = __expf(-sp2 * INV2SS2 - diff2 * inv2sr2);
                w[t]  = wt;
                den  += wt;
            }
        }
        const float invden = 1.0f / (den + 1e-8f);
        #pragma unroll
        for (int t = 0; t < 25; t++) s_w[clx][t][px] = w[t] * invden;
    }
    __syncthreads();

    // ---- phase 2: cell-centric weighted sums ----
    // thread = (cell, c4): one float4 channel group, all 16 pixels of the cell.
    const int cell = tid >> 4;           // 0..7
    const int c4   = tid & 15;           // 0..15
    const ulonglong2* sb = (const ulonglong2*)s_src + cell * ROW4 + c4;
    const unsigned long long* wb = (const unsigned long long*)&s_w[cell][0][0];

    // acc[j*4+c] = {out(px 2j, ch c), out(px 2j+1, ch c)} ; j=0..7 pixel pairs, c=0..3
    unsigned long long acc[32];
    #pragma unroll
    for (int i = 0; i < 32; i++) acc[i] = 0ULL;

    #pragma unroll
    for (int dy = 0; dy < 5; dy++) {
        #pragma unroll
        for (int dx = 0; dx < 5; dx++) {
            const int t = dy * 5 + dx;
            ulonglong2 sv = sb[(dy * XL + dx) * ROW4];     // LDS.128, 32 distinct lanes
            unsigned long long ss0, ss1, ss2, ss3;         // {s_c, s_c} packs
            asm("{\n\t.reg .b32 lo, hi;\n\t"
                "mov.b64 {lo, hi}, %2;\n\t"
                "mov.b64 %0, {lo, lo};\n\t"
                "mov.b64 %1, {hi, hi};\n\t}"
                : "=l"(ss0), "=l"(ss1) : "l"(sv.x));
            asm("{\n\t.reg .b32 lo, hi;\n\t"
                "mov.b64 {lo, hi}, %2;\n\t"
                "mov.b64 %0, {lo, lo};\n\t"
                "mov.b64 %1, {hi, hi};\n\t}"
                : "=l"(ss2), "=l"(ss3) : "l"(sv.y));
            #pragma unroll
            for (int j = 0; j < 8; j++) {
                unsigned long long wp = wb[t * 16 / 2 + j];   // {w_2j, w_2j+1}
                asm("fma.rn.f32x2 %0, %1, %2, %0;" : "+l"(acc[j * 4 + 0]) : "l"(wp), "l"(ss0));
                asm("fma.rn.f32x2 %0, %1, %2, %0;" : "+l"(acc[j * 4 + 1]) : "l"(wp), "l"(ss1));
                asm("fma.rn.f32x2 %0, %1, %2, %0;" : "+l"(acc[j * 4 + 2]) : "l"(wp), "l"(ss2));
                asm("fma.rn.f32x2 %0, %1, %2, %0;" : "+l"(acc[j * 4 + 3]) : "l"(wp), "l"(ss3));
            }
        }
    }

    // ---- store: 16 STG.128, no repacking (pixel pairs are contiguous x) ----
    const int yb = cellY * 4;
    const int xs = (cx0 + cell) * 4;
    #pragma unroll
    for (int r2 = 0; r2 < 4; r2++) {
        #pragma unroll
        for (int c = 0; c < 4; c++) {
            const int ch = c4 * 4 + c;
            ulonglong2 v;
            v.x = acc[(r2 * 2 + 0) * 4 + c];
            v.y = acc[(r2 * 2 + 1) * 4 + c];
            *(ulonglong2*)&out[(((size_t)(b * C_ + ch)) * HH + (yb + r2)) * HH + xs] = v;
        }
    }
}

// ---------------- launch ----------------
extern "C" void kernel_launch(void* const* d_in, const int* in_sizes, int n_in,
                              void* d_out, int out_size) {
    const float* src  = (const float*)d_in[0];
    const float* guid = (const float*)d_in[1];
    if (n_in >= 2 && in_sizes[0] == B_ * GN) {
        const float* tmp = src; src = guid; guid = tmp;
    }
    float* out = (float*)d_out;

    jbu_pre<<<dim3(128, 3, B_), 256>>>(guid, src);
    jbu_main<<<dim3(HL / CELLS, HL, B_), 128>>>(guid, out);
}

// round 7
// speedup vs baseline: 2.7013x; 1.1884x over previous
#include <cuda_runtime.h>
#include <cstdint>

// Problem constants
#define B_   4
#define C_   64
#define HL   64      // low-res h = w
#define HH   256     // high-res H = W
#define NPIX (HH*HH)
#define GN   (3*HH*HH)
#define INV2SS2 0.08f        // 1/(2*2.5^2)

// s_src layout: [c4 plane][pos], pos = dy*20 + xl (100 used, pad to 101)
// -> warp's 8 distinct tap addresses are 8 CONSECUTIVE float4s (one 128B segment)
#define ROWP 101

// ---------------- scratch ----------------
__device__ float g_part[B_][64][2];          // per-block partial (sum, sumsq)
__device__ float g_srcT[B_ * HL * HL * C_];  // source transposed to (b,y,x,c)

// ---------------- fused pre-pass: guidance reduction + source transpose ----------------
// grid (128, 3, B): y==2 -> reduce (x<64), y<2 -> transpose (c0 = y*32)
__global__ __launch_bounds__(256) void jbu_pre(const float* __restrict__ guid,
                                               const float* __restrict__ src) {
    const int b   = blockIdx.z;
    const int tid = threadIdx.x;

    if (blockIdx.y == 2) {
        if (blockIdx.x >= 64) return;
        const float* p = guid + (size_t)b * GN + (size_t)blockIdx.x * (GN / 64);
        float s = 0.f, s2 = 0.f;
        for (int i = tid; i < GN / 64; i += 256) {
            float v = p[i];
            s += v; s2 += v * v;
        }
        #pragma unroll
        for (int o = 16; o; o >>= 1) {
            s  += __shfl_xor_sync(0xffffffffu, s,  o);
            s2 += __shfl_xor_sync(0xffffffffu, s2, o);
        }
        __shared__ float sh[8][2];
        const int w = tid >> 5;
        if ((tid & 31) == 0) { sh[w][0] = s; sh[w][1] = s2; }
        __syncthreads();
        if (tid == 0) {
            float ts = 0.f, ts2 = 0.f;
            #pragma unroll
            for (int i = 0; i < 8; i++) { ts += sh[i][0]; ts2 += sh[i][1]; }
            g_part[b][blockIdx.x][0] = ts;
            g_part[b][blockIdx.x][1] = ts2;
        }
    } else {
        __shared__ float tile[32][33];
        const int p0 = blockIdx.x * 32;         // pixel block (0..4095)
        const int c0 = blockIdx.y * 32;         // channel block
        const int tx = tid & 31, ty = tid >> 5; // 32 x 8
        #pragma unroll
        for (int i = 0; i < 32; i += 8)
            tile[ty + i][tx] = src[((size_t)b * C_ + (c0 + ty + i)) * (HL * HL) + (p0 + tx)];
        __syncthreads();
        #pragma unroll
        for (int i = 0; i < 32; i += 8)
            g_srcT[((size_t)b * (HL * HL) + (p0 + ty + i)) * C_ + (c0 + tx)] = tile[tx][ty + i];
    }
}

// ---------------- main JBU kernel ----------------
// Block: 256 threads, output tile = 4 rows x 64 cols (16 low-res cells).
// Grid: (HH/64=4, HH/4=64, B)
__global__ __launch_bounds__(256) void jbu_main(
    const float* __restrict__ guid,   // (4,3,256,256)
    float* __restrict__ out)          // (4,64,256,256)
{
    const int b     = blockIdx.z;
    const int cellY = blockIdx.y;         // 0..63
    const int cx0   = blockIdx.x * 16;    // first low-res cell x
    const int x0    = cx0 * 4;

    __shared__ __align__(16) float s_src[16 * ROWP * 4];   // 25856 B, [c4][pos]
    __shared__ float s_gl[3][5][20];                       // g_low tile
    __shared__ float s_invsh;

    const int tid = threadIdx.x;

    // preload g_low tile: g_low[b][c][yi][xi] = guid[b][c][4*yi+2][4*xi+2]
    for (int i = tid; i < 300; i += 256) {
        int c  = i / 100;
        int rm = i % 100;
        int yl = rm / 20, xl = rm % 20;
        int yi = min(max(cellY + yl - 2, 0), HL - 1);
        int xi = min(max(cx0   + xl - 2, 0), HL - 1);
        s_gl[c][yl][xl] = guid[(((size_t)b * 3 + c) * HH + (4 * yi + 2)) * HH + (4 * xi + 2)];
    }

    // preload src tile, transposed layout: dp[c4 * ROWP + pos]
    {
        const float4* sp = (const float4*)g_srcT;
        float4*       dp = (float4*)s_src;
        for (int i = tid; i < 1600; i += 256) {
            int p  = i >> 4, c4 = i & 15;
            int yl = p / 20, xl = p % 20;
            int yi = min(max(cellY + yl - 2, 0), HL - 1);
            int xi = min(max(cx0   + xl - 2, 0), HL - 1);
            dp[c4 * ROWP + p] = sp[((((size_t)b * HL + yi) * HL + xi) << 4) + c4];
        }
    }

    // sigma finalization (warp 0, deterministic double shfl-tree)
    if (tid < 32) {
        double s  = (double)g_part[b][2 * tid][0] + (double)g_part[b][2 * tid + 1][0];
        double s2 = (double)g_part[b][2 * tid][1] + (double)g_part[b][2 * tid + 1][1];
        #pragma unroll
        for (int o = 16; o; o >>= 1) {
            s  += __shfl_xor_sync(0xffffffffu, s,  o);
            s2 += __shfl_xor_sync(0xffffffffu, s2, o);
        }
        if (tid == 0) {
            const double N = (double)GN;
            double var = (s2 - s * s / N) / (N - 1.0);
            s_invsh = (float)(2.0 / var);   // 1/(2*(0.5*sigma)^2) = 2/var
        }
    }
    __syncthreads();

    // ---- phase 1: per-pixel weights (registers) ----
    const int r   = tid >> 6;        // 0..3
    const int col = tid & 63;        // 0..63
    const int y   = cellY * 4 + r;
    const int x   = x0 + col;
    const int clx = col >> 2;        // local cell 0..15
    const float inv2sr2 = s_invsh;

    const float g0 = guid[(((size_t)b * 3 + 0) * HH + y) * HH + x];
    const float g1 = guid[(((size_t)b * 3 + 1) * HH + y) * HH + x];
    const float g2 = guid[(((size_t)b * 3 + 2) * HH + y) * HH + x];

    float w[25];
    float den = 0.f;
    #pragma unroll
    for (int dy = 0; dy < 5; dy++) {
        #pragma unroll
        for (int dx = 0; dx < 5; dx++) {
            const int t  = dy * 5 + dx;
            const int xl = clx + dx;
            float d0 = g0 - s_gl[0][dy][xl];
            float d1 = g1 - s_gl[1][dy][xl];
            float d2 = g2 - s_gl[2][dy][xl];
            float diff2 = d0 * d0 + d1 * d1 + d2 * d2;
            float sp2 = (float)((dy - 2) * (dy - 2) + (dx - 2) * (dx - 2));
            float wt = __expf(-sp2 * INV2SS2 - diff2 * inv2sr2);
            w[t]  = wt;
            den  += wt;
        }
    }
    const float invden = 1.0f / (den + 1e-8f);

    // pack weights as {w,w} for fma.rn.f32x2
    unsigned long long wp[25];
    #pragma unroll
    for (int t = 0; t < 25; t++) {
        float wv = w[t] * invden;
        asm("mov.b64 %0, {%1, %1};" : "=l"(wp[t]) : "f"(wv));
    }

    // ---- phase 2: weighted channel sums via packed f32x2 FMA ----
    // warp footprint per tap: 8 consecutive float4s = 128B, conflict-free, 4x broadcast
    float* op = out + (((size_t)b * C_) * HH + y) * HH + x;
    const ulonglong2* sb = (const ulonglong2*)s_src + clx;
    for (int cg = 0; cg < 16; cg++) {
        unsigned long long axy = 0ULL, azw = 0ULL;
        const ulonglong2* p = sb + cg * ROWP;
        #pragma unroll
        for (int dy = 0; dy < 5; dy++) {
            #pragma unroll
            for (int dx = 0; dx < 5; dx++) {
                const int t = dy * 5 + dx;
                ulonglong2 s = p[dy * 20 + dx];   // LDS.128, imm offset
                asm("fma.rn.f32x2 %0, %1, %2, %0;" : "+l"(axy) : "l"(wp[t]), "l"(s.x));
                asm("fma.rn.f32x2 %0, %1, %2, %0;" : "+l"(azw) : "l"(wp[t]), "l"(s.y));
            }
        }
        float ax, ay, az, aw;
        asm("mov.b64 {%0, %1}, %2;" : "=f"(ax), "=f"(ay) : "l"(axy));
        asm("mov.b64 {%0, %1}, %2;" : "=f"(az), "=f"(aw) : "l"(azw));
        op[(size_t)(4 * cg + 0) * NPIX] = ax;
        op[(size_t)(4 * cg + 1) * NPIX] = ay;
        op[(size_t)(4 * cg + 2) * NPIX] = az;
        op[(size_t)(4 * cg + 3) * NPIX] = aw;
    }
}

// ---------------- launch ----------------
extern "C" void kernel_launch(void* const* d_in, const int* in_sizes, int n_in,
                              void* d_out, int out_size) {
    const float* src  = (const float*)d_in[0];
    const float* guid = (const float*)d_in[1];
    if (n_in >= 2 && in_sizes[0] == B_ * GN) {
        const float* tmp = src; src = guid; guid = tmp;
    }
    float* out = (float*)d_out;

    jbu_pre<<<dim3(128, 3, B_), 256>>>(guid, src);
    jbu_main<<<dim3(HH / 64, HH / 4, B_), 256>>>(guid, out);
}